// round 2
// baseline (speedup 1.0000x reference)
#include <cuda_runtime.h>
#include <cstdint>

// ---------------------------------------------------------------------------
// SmallMLP_INR: fused 6-layer MLP. Base-target ISA only (no tcgen05 — the
// harness builds PTX at compute_103, which rejects arch-accelerated ops).
// Uses mma.sync m16n8k8 tf32 + cp.async double-buffered weight streaming.
// ---------------------------------------------------------------------------

#define THREADS 256
#define TILE_M  128
#define KDIM    256
#define NDIM    256
#define CHUNK   32

// strides (floats) chosen so lane addresses are conflict-free (mod 32 == 4)
#define A_STRIDE 260
#define B_STRIDE 36

// SMEM layout (bytes)
#define SM_W1    0        // 512 f
#define SM_B1    2048
#define SM_B2    3072
#define SM_B3    4096
#define SM_B4    5120
#define SM_B5    6144
#define SM_W6    7168
#define SM_B6    8192
#define SM_PART  8208     // 4*128 f
#define SM_A     10496    // 128*260*4 = 133120
#define SM_BW0   143616   // 256*36*4  = 36864
#define SM_BW1   180480   // 36864
#define SMEM_TOTAL 217344

// Pre-transposed, tf32-rounded weights: g_Wt[l][n*256 + k] = rn_tf32(W_{l+2}[k][n])
__device__ float g_Wt[4][KDIM * NDIM];

// ---------------------------------------------------------------------------
__device__ __forceinline__ uint32_t f2tf32(float x) {
    uint32_t y;
    asm("cvt.rna.tf32.f32 %0, %1;" : "=r"(y) : "f"(x));
    return y;
}
__device__ __forceinline__ float f2tf32f(float x) { return __uint_as_float(f2tf32(x)); }

__device__ __forceinline__ uint32_t smem_u32(const void* p) {
    uint32_t a;
    asm("{ .reg .u64 t; cvta.to.shared.u64 t, %1; cvt.u32.u64 %0, t; }" : "=r"(a) : "l"(p));
    return a;
}

__device__ __forceinline__ void mma_tf32(float* c, const uint32_t* a, const uint32_t* b) {
    asm volatile(
        "mma.sync.aligned.m16n8k8.row.col.f32.tf32.tf32.f32 "
        "{%0,%1,%2,%3}, {%4,%5,%6,%7}, {%8,%9}, {%0,%1,%2,%3};\n"
        : "+f"(c[0]), "+f"(c[1]), "+f"(c[2]), "+f"(c[3])
        : "r"(a[0]), "r"(a[1]), "r"(a[2]), "r"(a[3]), "r"(b[0]), "r"(b[1]));
}

__device__ __forceinline__ void cp_async16(uint32_t dst, const void* src) {
    asm volatile("cp.async.cg.shared.global [%0], [%1], 16;" :: "r"(dst), "l"(src) : "memory");
}
__device__ __forceinline__ void cp_commit() { asm volatile("cp.async.commit_group;" ::: "memory"); }
__device__ __forceinline__ void cp_wait1()  { asm volatile("cp.async.wait_group 1;" ::: "memory"); }
__device__ __forceinline__ void cp_wait0()  { asm volatile("cp.async.wait_group 0;" ::: "memory"); }

// One K-chunk of transposed weights: 256 n-rows x 32 k (128B/row) -> padded SMEM.
__device__ __forceinline__ void load_chunk(uint32_t dst_base, const float* Wt,
                                           int k0, int tid) {
    uint32_t dst = dst_base + (uint32_t)tid * (B_STRIDE * 4);
    const float* src = Wt + (size_t)tid * KDIM + k0;
#pragma unroll
    for (int j = 0; j < 8; j++)
        cp_async16(dst + j * 16, src + j * 4);
}

// ---------------------------------------------------------------------------
// weight pre-transpose (+ tf32 round)
// ---------------------------------------------------------------------------
__global__ void transpose_w_kernel(const float* __restrict__ W2, const float* __restrict__ W3,
                                   const float* __restrict__ W4, const float* __restrict__ W5) {
    __shared__ float t[32][33];
    const float* W = (blockIdx.z == 0) ? W2 : (blockIdx.z == 1) ? W3
                   : (blockIdx.z == 2) ? W4 : W5;
    const int nb = blockIdx.x * 32, kb = blockIdx.y * 32;
    const int tx = threadIdx.x, ty = threadIdx.y;
#pragma unroll
    for (int i = 0; i < 32; i += 8)
        t[ty + i][tx] = W[(size_t)(kb + ty + i) * 256 + (nb + tx)];
    __syncthreads();
    float* dst = g_Wt[blockIdx.z];
#pragma unroll
    for (int i = 0; i < 32; i += 8)
        dst[(size_t)(nb + ty + i) * 256 + (kb + tx)] = f2tf32f(t[tx][ty + i]);
}

// ---------------------------------------------------------------------------
// main fused kernel: one CTA = 128 rows end-to-end
// ---------------------------------------------------------------------------
__global__ void __launch_bounds__(THREADS, 1) mlp_kernel(
    const float* __restrict__ coords,
    const float* __restrict__ W1, const float* __restrict__ b1,
    const float* __restrict__ b2, const float* __restrict__ b3,
    const float* __restrict__ b4, const float* __restrict__ b5,
    const float* __restrict__ W6, const float* __restrict__ b6,
    float* __restrict__ out) {
    extern __shared__ __align__(16) char smem[];
    const uint32_t sb = smem_u32(smem);
    const int tid = threadIdx.x;
    const int wid = tid >> 5;
    const int lid = tid & 31;
    const int g = lid >> 2;       // groupID
    const int t = lid & 3;        // threadID_in_group
    const int mrow = (wid & 1) * 64;
    const int ncol = (wid >> 1) * 64;
    const int row_base = blockIdx.x * TILE_M;

    float* sW1 = (float*)(smem + SM_W1);
    float* sB1 = (float*)(smem + SM_B1);
    float* sB2 = (float*)(smem + SM_B2);
    float* sB3 = (float*)(smem + SM_B3);
    float* sB4 = (float*)(smem + SM_B4);
    float* sB5 = (float*)(smem + SM_B5);
    float* sW6 = (float*)(smem + SM_W6);
    float* sB6 = (float*)(smem + SM_B6);
    float* sPart = (float*)(smem + SM_PART);
    float* sA  = (float*)(smem + SM_A);

    // stage small params
    sW1[tid]       = W1[tid];
    sW1[tid + 256] = W1[tid + 256];
    sB1[tid] = b1[tid];
    sB2[tid] = b2[tid];
    sB3[tid] = b3[tid];
    sB4[tid] = b4[tid];
    sB5[tid] = b5[tid];
    sW6[tid] = f2tf32f(W6[tid]) ;  // rounding W6 harmless (FFMA path), keep full: actually keep exact
    if (tid == 0) sB6[0] = b6[0];
    // overwrite with exact W6 (FFMA epilogue needs no tf32 rounding)
    sW6[tid] = W6[tid];

    // prefetch first two weight chunks of layer 2 (overlaps with layer 1 math)
    load_chunk(sb + SM_BW0, g_Wt[0], 0, tid);      cp_commit();
    load_chunk(sb + SM_BW1, g_Wt[0], CHUNK, tid);  cp_commit();

    __syncthreads();

    // ---- Layer 1 (fan-in 2, FFMA) -> sA (tf32-rounded) ----
    {
        const int row = tid >> 1;
        const int j0  = (tid & 1) * 128;
        const float2 c = *(const float2*)(coords + 2 * (size_t)(row_base + row));
        float* dst = sA + (size_t)row * A_STRIDE;
#pragma unroll
        for (int j = 0; j < 128; j += 4) {
            const int jj = j0 + j;
            float4 v;
            v.x = f2tf32f(fmaxf(fmaf(c.x, sW1[jj + 0], fmaf(c.y, sW1[256 + jj + 0], sB1[jj + 0])), 0.f));
            v.y = f2tf32f(fmaxf(fmaf(c.x, sW1[jj + 1], fmaf(c.y, sW1[256 + jj + 1], sB1[jj + 1])), 0.f));
            v.z = f2tf32f(fmaxf(fmaf(c.x, sW1[jj + 2], fmaf(c.y, sW1[256 + jj + 2], sB1[jj + 2])), 0.f));
            v.w = f2tf32f(fmaxf(fmaf(c.x, sW1[jj + 3], fmaf(c.y, sW1[256 + jj + 3], sB1[jj + 3])), 0.f));
            *(float4*)(dst + jj) = v;
        }
    }
    __syncthreads();

    // ---- Layers 2..5: 128x256 @ 256x256 via mma.sync tf32, double-buffered W ----
#pragma unroll 1
    for (int l = 0; l < 4; l++) {
        float acc[4][8][4];
#pragma unroll
        for (int i = 0; i < 4; i++)
#pragma unroll
            for (int j = 0; j < 8; j++)
#pragma unroll
                for (int c = 0; c < 4; c++) acc[i][j][c] = 0.f;

#pragma unroll 1
        for (int cc = 0; cc < 8; cc++) {
            if (l == 3 && cc == 7) cp_wait0(); else cp_wait1();
            __syncthreads();

            const float* sBuf = (float*)(smem + ((cc & 1) ? SM_BW1 : SM_BW0));
#pragma unroll
            for (int ks = 0; ks < 4; ks++) {
                const int k0 = cc * CHUNK + ks * 8;
                uint32_t a[4][4];
#pragma unroll
                for (int i = 0; i < 4; i++) {
                    const float* p  = sA + (size_t)(mrow + 16 * i + g) * A_STRIDE + k0 + t;
                    const float* p8 = p + 8 * A_STRIDE;
                    a[i][0] = __float_as_uint(p[0]);
                    a[i][1] = __float_as_uint(p8[0]);
                    a[i][2] = __float_as_uint(p[4]);
                    a[i][3] = __float_as_uint(p8[4]);
                }
                uint32_t b[8][2];
#pragma unroll
                for (int j = 0; j < 8; j++) {
                    const float* q = sBuf + (size_t)(ncol + 8 * j + g) * B_STRIDE + ks * 8 + t;
                    b[j][0] = __float_as_uint(q[0]);
                    b[j][1] = __float_as_uint(q[4]);
                }
#pragma unroll
                for (int i = 0; i < 4; i++)
#pragma unroll
                    for (int j = 0; j < 8; j++)
                        mma_tf32(acc[i][j], a[i], b[j]);
            }
            __syncthreads();

            const int q = l * 8 + cc + 2;   // flat next-chunk index
            if (q < 32) {
                load_chunk(sb + ((q & 1) ? SM_BW1 : SM_BW0), g_Wt[q >> 3],
                           (q & 7) * CHUNK, tid);
                cp_commit();
            }
        }

        if (l < 3) {
            // epilogue: sA <- rn_tf32(relu(D + bias))
            const float* bias = (l == 0) ? sB2 : (l == 1) ? sB3 : sB4;
#pragma unroll
            for (int j = 0; j < 8; j++) {
                const int col = ncol + 8 * j + 2 * t;
                const float bs0 = bias[col], bs1 = bias[col + 1];
#pragma unroll
                for (int i = 0; i < 4; i++) {
                    const int row = mrow + 16 * i + g;
                    float2 v0, v1;
                    v0.x = f2tf32f(fmaxf(acc[i][j][0] + bs0, 0.f));
                    v0.y = f2tf32f(fmaxf(acc[i][j][1] + bs1, 0.f));
                    v1.x = f2tf32f(fmaxf(acc[i][j][2] + bs0, 0.f));
                    v1.y = f2tf32f(fmaxf(acc[i][j][3] + bs1, 0.f));
                    *(float2*)(sA + (size_t)row * A_STRIDE + col) = v0;
                    *(float2*)(sA + (size_t)(row + 8) * A_STRIDE + col) = v1;
                }
            }
            __syncthreads();
        } else {
            // ---- Layer 6: out = relu(D + b5) . W6 + b6 ----
            float r0[4] = {0.f, 0.f, 0.f, 0.f};
            float r1[4] = {0.f, 0.f, 0.f, 0.f};
#pragma unroll
            for (int j = 0; j < 8; j++) {
                const int col = ncol + 8 * j + 2 * t;
                const float w0 = sW6[col], w1 = sW6[col + 1];
                const float s0 = sB5[col], s1 = sB5[col + 1];
#pragma unroll
                for (int i = 0; i < 4; i++) {
                    r0[i] = fmaf(fmaxf(acc[i][j][0] + s0, 0.f), w0, r0[i]);
                    r0[i] = fmaf(fmaxf(acc[i][j][1] + s1, 0.f), w1, r0[i]);
                    r1[i] = fmaf(fmaxf(acc[i][j][2] + s0, 0.f), w0, r1[i]);
                    r1[i] = fmaf(fmaxf(acc[i][j][3] + s1, 0.f), w1, r1[i]);
                }
            }
#pragma unroll
            for (int d = 1; d <= 2; d <<= 1) {
#pragma unroll
                for (int i = 0; i < 4; i++) {
                    r0[i] += __shfl_xor_sync(0xFFFFFFFFu, r0[i], d);
                    r1[i] += __shfl_xor_sync(0xFFFFFFFFu, r1[i], d);
                }
            }
            if (t == 0) {
                float* part = sPart + (wid >> 1) * 128;
#pragma unroll
                for (int i = 0; i < 4; i++) {
                    part[mrow + 16 * i + g]     = r0[i];
                    part[mrow + 16 * i + g + 8] = r1[i];
                }
            }
            __syncthreads();
            if (tid < TILE_M)
                out[row_base + tid] = sPart[tid] + sPart[128 + tid] +
                                      sPart[256 + tid] + sPart[384 + tid] + sB6[0];
        }
    }
}

// ---------------------------------------------------------------------------
extern "C" void kernel_launch(void* const* d_in, const int* in_sizes, int n_in,
                              void* d_out, int out_size) {
    const float* coords = (const float*)d_in[0];
    const float* W1 = (const float*)d_in[1];
    const float* b1 = (const float*)d_in[2];
    const float* W2 = (const float*)d_in[3];
    const float* b2 = (const float*)d_in[4];
    const float* W3 = (const float*)d_in[5];
    const float* b3 = (const float*)d_in[6];
    const float* W4 = (const float*)d_in[7];
    const float* b4 = (const float*)d_in[8];
    const float* W5 = (const float*)d_in[9];
    const float* b5 = (const float*)d_in[10];
    const float* W6 = (const float*)d_in[11];
    const float* b6 = (const float*)d_in[12];
    float* out = (float*)d_out;

    const int n = in_sizes[0] / 2;  // rows

    transpose_w_kernel<<<dim3(NDIM / 32, KDIM / 32, 4), dim3(32, 8)>>>(W2, W3, W4, W5);

    cudaFuncSetAttribute(mlp_kernel, cudaFuncAttributeMaxDynamicSharedMemorySize, SMEM_TOTAL);
    mlp_kernel<<<n / TILE_M, THREADS, SMEM_TOTAL>>>(coords, W1, b1, b2, b3, b4, b5,
                                                    W6, b6, out);
}

// round 3
// speedup vs baseline: 1.9458x; 1.9458x over previous
#include <cuda_runtime.h>
#include <cuda_fp16.h>
#include <cstdint>

// ---------------------------------------------------------------------------
// SmallMLP_INR: fused 6-layer MLP. Base-target ISA (compute_103-safe).
// fp16 m16n8k16 mma.sync + ldmatrix + cp.async double-buffered weights.
// fp16 operands carry the same 11-bit significand as tf32; accum is fp32.
// ---------------------------------------------------------------------------

#define THREADS 256
#define TILE_M  128
#define KDIM    256
#define NDIM    256
#define CHUNK   64          // K per streamed weight chunk
#define NCHUNKS 16          // 4 layers * 4 chunks

// strides in fp16 elements; both give row-stride % 128B == 16B -> ldmatrix
// conflict-free (8 rows land on 8 distinct 16B segments of the 128B wrap)
#define A_STRIDE 264        // 256 + 8  (528 bytes)
#define B_STRIDE 72         // 64 + 8   (144 bytes)

// SMEM layout (bytes)
#define SM_W1    0          // 512 f32
#define SM_B1    2048
#define SM_B2    3072
#define SM_B3    4096
#define SM_B4    5120
#define SM_B5    6144
#define SM_W6    7168
#define SM_B6    8192
#define SM_PART  8208       // 4*128 f32
#define SM_A     10496      // 128*264*2 = 67584   (128B aligned)
#define SM_BW0   78080      // 256*72*2  = 36864   (128B aligned)
#define SM_BW1   114944     // 36864
#define SMEM_TOTAL 151808

// Pre-transposed fp16 weights: g_WtH[l][n*256 + k] = (half)W_{l+2}[k][n]
__device__ __half g_WtH[4][KDIM * NDIM];

// ---------------------------------------------------------------------------
__device__ __forceinline__ uint32_t smem_u32(const void* p) {
    uint32_t a;
    asm("{ .reg .u64 t; cvta.to.shared.u64 t, %1; cvt.u32.u64 %0, t; }" : "=r"(a) : "l"(p));
    return a;
}

__device__ __forceinline__ void mma_f16(float* c, const uint32_t* a, const uint32_t* b) {
    asm volatile(
        "mma.sync.aligned.m16n8k16.row.col.f32.f16.f16.f32 "
        "{%0,%1,%2,%3}, {%4,%5,%6,%7}, {%8,%9}, {%0,%1,%2,%3};\n"
        : "+f"(c[0]), "+f"(c[1]), "+f"(c[2]), "+f"(c[3])
        : "r"(a[0]), "r"(a[1]), "r"(a[2]), "r"(a[3]), "r"(b[0]), "r"(b[1]));
}

#define LDMATRIX_X4(r0, r1, r2, r3, addr) \
    asm volatile("ldmatrix.sync.aligned.m8n8.x4.shared.b16 {%0,%1,%2,%3}, [%4];" \
                 : "=r"(r0), "=r"(r1), "=r"(r2), "=r"(r3) : "r"(addr))

__device__ __forceinline__ void cp_async16(uint32_t dst, const void* src) {
    asm volatile("cp.async.cg.shared.global [%0], [%1], 16;" :: "r"(dst), "l"(src) : "memory");
}
__device__ __forceinline__ void cp_commit() { asm volatile("cp.async.commit_group;" ::: "memory"); }
__device__ __forceinline__ void cp_wait1()  { asm volatile("cp.async.wait_group 1;" ::: "memory"); }
__device__ __forceinline__ void cp_wait0()  { asm volatile("cp.async.wait_group 0;" ::: "memory"); }

// One K-chunk: 256 n-rows x 64 k-halves (128B/row) -> padded SMEM buffer.
__device__ __forceinline__ void load_chunk(uint32_t dst_base, const __half* Wt,
                                           int k0, int tid) {
    uint32_t dst = dst_base + (uint32_t)tid * (B_STRIDE * 2);
    const __half* src = Wt + (size_t)tid * KDIM + k0;
#pragma unroll
    for (int j = 0; j < 8; j++)
        cp_async16(dst + j * 16, src + j * 8);
}

// ---------------------------------------------------------------------------
// weight pre-transpose + fp16 round: g_WtH[l][n*256+k] = (half)W[k*256+n]
// ---------------------------------------------------------------------------
__global__ void transpose_w_kernel(const float* __restrict__ W2, const float* __restrict__ W3,
                                   const float* __restrict__ W4, const float* __restrict__ W5) {
    __shared__ float t[32][33];
    const float* W = (blockIdx.z == 0) ? W2 : (blockIdx.z == 1) ? W3
                   : (blockIdx.z == 2) ? W4 : W5;
    const int nb = blockIdx.x * 32, kb = blockIdx.y * 32;
    const int tx = threadIdx.x, ty = threadIdx.y;
#pragma unroll
    for (int i = 0; i < 32; i += 8)
        t[ty + i][tx] = W[(size_t)(kb + ty + i) * 256 + (nb + tx)];
    __syncthreads();
    __half* dst = g_WtH[blockIdx.z];
#pragma unroll
    for (int i = 0; i < 32; i += 8)
        dst[(size_t)(nb + ty + i) * 256 + (kb + tx)] = __float2half_rn(t[tx][ty + i]);
}

// ---------------------------------------------------------------------------
// main fused kernel: one CTA = 128 rows end-to-end
// ---------------------------------------------------------------------------
__global__ void __launch_bounds__(THREADS, 1) mlp_kernel(
    const float* __restrict__ coords,
    const float* __restrict__ W1, const float* __restrict__ b1,
    const float* __restrict__ b2, const float* __restrict__ b3,
    const float* __restrict__ b4, const float* __restrict__ b5,
    const float* __restrict__ W6, const float* __restrict__ b6,
    float* __restrict__ out) {
    extern __shared__ __align__(128) char smem[];
    const uint32_t sb = smem_u32(smem);
    const int tid = threadIdx.x;
    const int wid = tid >> 5;
    const int lid = tid & 31;
    const int g = lid >> 2;
    const int t = lid & 3;
    const int mrow = (wid & 1) * 64;      // 2 M-slots of 64 rows
    const int ncol = (wid >> 1) * 64;     // 4 N-slots of 64 cols
    const int row_base = blockIdx.x * TILE_M;

    float* sW1 = (float*)(smem + SM_W1);
    float* sB1 = (float*)(smem + SM_B1);
    float* sB2 = (float*)(smem + SM_B2);
    float* sB3 = (float*)(smem + SM_B3);
    float* sB4 = (float*)(smem + SM_B4);
    float* sB5 = (float*)(smem + SM_B5);
    float* sW6 = (float*)(smem + SM_W6);
    float* sB6 = (float*)(smem + SM_B6);
    float* sPart = (float*)(smem + SM_PART);
    __half* sA = (__half*)(smem + SM_A);

    sW1[tid]       = W1[tid];
    sW1[tid + 256] = W1[tid + 256];
    sB1[tid] = b1[tid];
    sB2[tid] = b2[tid];
    sB3[tid] = b3[tid];
    sB4[tid] = b4[tid];
    sB5[tid] = b5[tid];
    sW6[tid] = W6[tid];
    if (tid == 0) sB6[0] = b6[0];

    // prefetch first two weight chunks of layer 2 (overlaps layer-1 math)
    load_chunk(sb + SM_BW0, g_WtH[0], 0, tid);      cp_commit();
    load_chunk(sb + SM_BW1, g_WtH[0], CHUNK, tid);  cp_commit();

    __syncthreads();

    // ---- Layer 1 (fan-in 2, FFMA) -> sA (fp16) ----
    {
        const int row = tid >> 1;
        const int j0  = (tid & 1) * 128;
        const float2 c = *(const float2*)(coords + 2 * (size_t)(row_base + row));
        __half* dst = sA + (size_t)row * A_STRIDE;
#pragma unroll
        for (int j = 0; j < 128; j += 2) {
            const int jj = j0 + j;
            float v0 = fmaxf(fmaf(c.x, sW1[jj + 0], fmaf(c.y, sW1[256 + jj + 0], sB1[jj + 0])), 0.f);
            float v1 = fmaxf(fmaf(c.x, sW1[jj + 1], fmaf(c.y, sW1[256 + jj + 1], sB1[jj + 1])), 0.f);
            *(__half2*)(dst + jj) = __floats2half2_rn(v0, v1);
        }
    }
    __syncthreads();

    // precomputed ldmatrix lane-address components
    // A: lanes 0-7 rows +0..7 @k0 | 8-15 rows +8..15 @k0 | 16-23 rows +0..7 @k0+8 | 24-31 rows +8..15 @k0+8
    const uint32_t aA = sb + SM_A +
        (uint32_t)(((mrow + (lid & 15)) * A_STRIDE + ((lid & 16) ? 8 : 0)) * 2);
    // B: lanes 0-7 n+0..7 @k0 | 8-15 n+0..7 @k0+8 | 16-23 n+8..15 @k0 | 24-31 n+8..15 @k0+8
    const uint32_t bOff =
        (uint32_t)((ncol + (lid & 7) + ((lid & 16) ? 8 : 0)) * B_STRIDE * 2 +
                   ((lid & 8) ? 16 : 0));

    // ---- Layers 2..5: 128x256 @ 256x256, fp16 m16n8k16, double-buffered W ----
#pragma unroll 1
    for (int l = 0; l < 4; l++) {
        float acc[4][8][4];
#pragma unroll
        for (int i = 0; i < 4; i++)
#pragma unroll
            for (int j = 0; j < 8; j++)
#pragma unroll
                for (int c = 0; c < 4; c++) acc[i][j][c] = 0.f;

#pragma unroll 1
        for (int cc = 0; cc < 4; cc++) {
            const int f = l * 4 + cc;                 // flat chunk index
            if (f == NCHUNKS - 1) cp_wait0(); else cp_wait1();
            __syncthreads();

            const uint32_t bB = ((f & 1) ? (sb + SM_BW1) : (sb + SM_BW0)) + bOff;
#pragma unroll
            for (int ks = 0; ks < 4; ks++) {          // 4 k16-steps per 64-chunk
                const int k0 = cc * CHUNK + ks * 16;
                uint32_t a[4][4];
#pragma unroll
                for (int i = 0; i < 4; i++) {
                    const uint32_t addr = aA + (uint32_t)(i * 16 * A_STRIDE + k0) * 2;
                    LDMATRIX_X4(a[i][0], a[i][1], a[i][2], a[i][3], addr);
                }
                uint32_t b[4][4];
#pragma unroll
                for (int jp = 0; jp < 4; jp++) {
                    const uint32_t addr = bB + (uint32_t)(jp * 16 * B_STRIDE + ks * 16) * 2;
                    LDMATRIX_X4(b[jp][0], b[jp][1], b[jp][2], b[jp][3], addr);
                }
#pragma unroll
                for (int i = 0; i < 4; i++)
#pragma unroll
                    for (int j = 0; j < 8; j++)
                        mma_f16(acc[i][j], a[i], &b[j >> 1][(j & 1) * 2]);
            }
            __syncthreads();

            const int q = f + 2;                      // next chunk to prefetch
            if (q < NCHUNKS) {
                load_chunk(sb + ((q & 1) ? SM_BW1 : SM_BW0), g_WtH[q >> 2],
                           (q & 3) * CHUNK, tid);
                cp_commit();
            }
        }

        if (l < 3) {
            // epilogue: sA <- (half)relu(D + bias)
            const float* bias = (l == 0) ? sB2 : (l == 1) ? sB3 : sB4;
#pragma unroll
            for (int j = 0; j < 8; j++) {
                const int col = ncol + 8 * j + 2 * t;
                const float bs0 = bias[col], bs1 = bias[col + 1];
#pragma unroll
                for (int i = 0; i < 4; i++) {
                    const int row = mrow + 16 * i + g;
                    *(__half2*)(sA + (size_t)row * A_STRIDE + col) =
                        __floats2half2_rn(fmaxf(acc[i][j][0] + bs0, 0.f),
                                          fmaxf(acc[i][j][1] + bs1, 0.f));
                    *(__half2*)(sA + (size_t)(row + 8) * A_STRIDE + col) =
                        __floats2half2_rn(fmaxf(acc[i][j][2] + bs0, 0.f),
                                          fmaxf(acc[i][j][3] + bs1, 0.f));
                }
            }
            __syncthreads();
        } else {
            // ---- Layer 6: out = relu(D + b5) . W6 + b6 (fp32 FFMA) ----
            float r0[4] = {0.f, 0.f, 0.f, 0.f};
            float r1[4] = {0.f, 0.f, 0.f, 0.f};
#pragma unroll
            for (int j = 0; j < 8; j++) {
                const int col = ncol + 8 * j + 2 * t;
                const float w0 = sW6[col], w1 = sW6[col + 1];
                const float s0 = sB5[col], s1 = sB5[col + 1];
#pragma unroll
                for (int i = 0; i < 4; i++) {
                    r0[i] = fmaf(fmaxf(acc[i][j][0] + s0, 0.f), w0, r0[i]);
                    r0[i] = fmaf(fmaxf(acc[i][j][1] + s1, 0.f), w1, r0[i]);
                    r1[i] = fmaf(fmaxf(acc[i][j][2] + s0, 0.f), w0, r1[i]);
                    r1[i] = fmaf(fmaxf(acc[i][j][3] + s1, 0.f), w1, r1[i]);
                }
            }
#pragma unroll
            for (int d = 1; d <= 2; d <<= 1) {
#pragma unroll
                for (int i = 0; i < 4; i++) {
                    r0[i] += __shfl_xor_sync(0xFFFFFFFFu, r0[i], d);
                    r1[i] += __shfl_xor_sync(0xFFFFFFFFu, r1[i], d);
                }
            }
            if (t == 0) {
                float* part = sPart + (wid >> 1) * 128;
#pragma unroll
                for (int i = 0; i < 4; i++) {
                    part[mrow + 16 * i + g]     = r0[i];
                    part[mrow + 16 * i + g + 8] = r1[i];
                }
            }
            __syncthreads();
            if (tid < TILE_M)
                out[row_base + tid] = sPart[tid] + sPart[128 + tid] +
                                      sPart[256 + tid] + sPart[384 + tid] + sB6[0];
        }
    }
}

// ---------------------------------------------------------------------------
extern "C" void kernel_launch(void* const* d_in, const int* in_sizes, int n_in,
                              void* d_out, int out_size) {
    const float* coords = (const float*)d_in[0];
    const float* W1 = (const float*)d_in[1];
    const float* b1 = (const float*)d_in[2];
    const float* W2 = (const float*)d_in[3];
    const float* b2 = (const float*)d_in[4];
    const float* W3 = (const float*)d_in[5];
    const float* b3 = (const float*)d_in[6];
    const float* W4 = (const float*)d_in[7];
    const float* b4 = (const float*)d_in[8];
    const float* W5 = (const float*)d_in[9];
    const float* b5 = (const float*)d_in[10];
    const float* W6 = (const float*)d_in[11];
    const float* b6 = (const float*)d_in[12];
    float* out = (float*)d_out;

    const int n = in_sizes[0] / 2;  // rows

    transpose_w_kernel<<<dim3(NDIM / 32, KDIM / 32, 4), dim3(32, 8)>>>(W2, W3, W4, W5);

    cudaFuncSetAttribute(mlp_kernel, cudaFuncAttributeMaxDynamicSharedMemorySize, SMEM_TOTAL);
    mlp_kernel<<<n / TILE_M, THREADS, SMEM_TOTAL>>>(coords, W1, b1, b2, b3, b4, b5,
                                                    W6, b6, out);
}

// round 4
// speedup vs baseline: 2.2970x; 1.1805x over previous
#include <cuda_runtime.h>
#include <cuda_fp16.h>
#include <cstdint>

// ---------------------------------------------------------------------------
// SmallMLP_INR: fused 6-layer MLP, base-target ISA (compute_103-safe).
// fp16 m16n8k16 mma.sync + ldmatrix. Warp-private weight pipelines:
// each warp owns a 32-col N-slice, streams its own B via cp.async and syncs
// only with itself (wait_group + syncwarp). No CTA barriers in the MMA loop.
// ---------------------------------------------------------------------------

#define THREADS 256
#define TILE_M  128
#define KDIM    256
#define NDIM    256

#define A_STRIDE 264   // halves; 528B row stride, %128B == 16 -> ldmatrix conflict-free
#define B_STRIDE 264

// SMEM layout (bytes)
#define SM_W1    0        // 512 f32
#define SM_B1    2048
#define SM_B2    3072
#define SM_B3    4096
#define SM_B4    5120
#define SM_B5    6144
#define SM_W6    7168
#define SM_B6    8192
#define SM_PART  8208     // 8*128 f32 = 4096
#define SM_A     12416    // 128*264*2 = 67584
#define SM_B     80000    // 256*264*2 = 135168
#define SMEM_TOTAL 215168

// Pre-transposed fp16 weights: g_WtH[l][n*256 + k] = (half)W_{l+2}[k][n]
__device__ __half g_WtH[4][KDIM * NDIM];

// ---------------------------------------------------------------------------
__device__ __forceinline__ uint32_t smem_u32(const void* p) {
    uint32_t a;
    asm("{ .reg .u64 t; cvta.to.shared.u64 t, %1; cvt.u32.u64 %0, t; }" : "=r"(a) : "l"(p));
    return a;
}

__device__ __forceinline__ void mma_f16(float* c, const uint32_t* a, const uint32_t* b) {
    asm volatile(
        "mma.sync.aligned.m16n8k16.row.col.f32.f16.f16.f32 "
        "{%0,%1,%2,%3}, {%4,%5,%6,%7}, {%8,%9}, {%0,%1,%2,%3};\n"
        : "+f"(c[0]), "+f"(c[1]), "+f"(c[2]), "+f"(c[3])
        : "r"(a[0]), "r"(a[1]), "r"(a[2]), "r"(a[3]), "r"(b[0]), "r"(b[1]));
}

#define LDMATRIX_X4(r0, r1, r2, r3, addr) \
    asm volatile("ldmatrix.sync.aligned.m8n8.x4.shared.b16 {%0,%1,%2,%3}, [%4];" \
                 : "=r"(r0), "=r"(r1), "=r"(r2), "=r"(r3) : "r"(addr))

__device__ __forceinline__ void cp_async16(uint32_t dst, const void* src) {
    asm volatile("cp.async.cg.shared.global [%0], [%1], 16;" :: "r"(dst), "l"(src) : "memory");
}
__device__ __forceinline__ void cp_commit() { asm volatile("cp.async.commit_group;" ::: "memory"); }
__device__ __forceinline__ void cp_wait(int n) {
    // n is compile-time constant at each call site after unrolling
    if (n == 0)      asm volatile("cp.async.wait_group 0;" ::: "memory");
    else if (n == 1) asm volatile("cp.async.wait_group 1;" ::: "memory");
    else if (n == 2) asm volatile("cp.async.wait_group 2;" ::: "memory");
    else             asm volatile("cp.async.wait_group 3;" ::: "memory");
}

// Warp-private: load chunk c (k in [64c,64c+64)) of this warp's 32-row B slice.
// lane r handles row nbase+r: 64 halves = 8 x 16B cp.async.
__device__ __forceinline__ void load_wchunk(uint32_t sbB, const __half* Wt,
                                            int nbase, int c, int lane) {
    const int row = nbase + lane;
    uint32_t dst = sbB + (uint32_t)(row * B_STRIDE + c * 64) * 2;
    const __half* src = Wt + (size_t)row * KDIM + c * 64;
#pragma unroll
    for (int j = 0; j < 8; j++)
        cp_async16(dst + j * 16, src + j * 8);
    cp_commit();
}

// ---------------------------------------------------------------------------
// weight pre-transpose + fp16 round
// ---------------------------------------------------------------------------
__global__ void transpose_w_kernel(const float* __restrict__ W2, const float* __restrict__ W3,
                                   const float* __restrict__ W4, const float* __restrict__ W5) {
    __shared__ float t[32][33];
    const float* W = (blockIdx.z == 0) ? W2 : (blockIdx.z == 1) ? W3
                   : (blockIdx.z == 2) ? W4 : W5;
    const int nb = blockIdx.x * 32, kb = blockIdx.y * 32;
    const int tx = threadIdx.x, ty = threadIdx.y;
#pragma unroll
    for (int i = 0; i < 32; i += 8)
        t[ty + i][tx] = W[(size_t)(kb + ty + i) * 256 + (nb + tx)];
    __syncthreads();
    __half* dst = g_WtH[blockIdx.z];
#pragma unroll
    for (int i = 0; i < 32; i += 8)
        dst[(size_t)(nb + ty + i) * 256 + (kb + tx)] = __float2half_rn(t[tx][ty + i]);
}

// ---------------------------------------------------------------------------
// main fused kernel: one CTA = 128 rows end-to-end; warp = 128xM x 32xN tile
// ---------------------------------------------------------------------------
__global__ void __launch_bounds__(THREADS, 1) mlp_kernel(
    const float* __restrict__ coords,
    const float* __restrict__ W1, const float* __restrict__ b1,
    const float* __restrict__ b2, const float* __restrict__ b3,
    const float* __restrict__ b4, const float* __restrict__ b5,
    const float* __restrict__ W6, const float* __restrict__ b6,
    float* __restrict__ out) {
    extern __shared__ __align__(128) char smem[];
    const uint32_t sb = smem_u32(smem);
    const int tid = threadIdx.x;
    const int wid = tid >> 5;
    const int lid = tid & 31;
    const int g = lid >> 2;          // groupID (0..7)
    const int t = lid & 3;           // thread-in-group
    const int nbase = wid * 32;      // this warp's private N slice
    const int row_base = blockIdx.x * TILE_M;

    float* sW1 = (float*)(smem + SM_W1);
    float* sB1 = (float*)(smem + SM_B1);
    float* sB2 = (float*)(smem + SM_B2);
    float* sB3 = (float*)(smem + SM_B3);
    float* sB4 = (float*)(smem + SM_B4);
    float* sB5 = (float*)(smem + SM_B5);
    float* sW6 = (float*)(smem + SM_W6);
    float* sB6 = (float*)(smem + SM_B6);
    float* sPart = (float*)(smem + SM_PART);
    __half* sA = (__half*)(smem + SM_A);

    // stage small params
    sW1[tid]       = W1[tid];
    sW1[tid + 256] = W1[tid + 256];
    sB1[tid] = b1[tid];
    sB2[tid] = b2[tid];
    sB3[tid] = b3[tid];
    sB4[tid] = b4[tid];
    sB5[tid] = b5[tid];
    sW6[tid] = W6[tid];
    if (tid == 0) sB6[0] = b6[0];

    // prologue: each warp streams its layer-2 B slice (4 chunk-groups)
    load_wchunk(sb + SM_B, g_WtH[0], nbase, 0, lid);
    load_wchunk(sb + SM_B, g_WtH[0], nbase, 1, lid);
    load_wchunk(sb + SM_B, g_WtH[0], nbase, 2, lid);
    load_wchunk(sb + SM_B, g_WtH[0], nbase, 3, lid);

    __syncthreads();

    // ---- Layer 1 (fan-in 2, FFMA) -> sA (fp16) ----
    {
        const int row = tid >> 1;
        const int j0  = (tid & 1) * 128;
        const float2 c = *(const float2*)(coords + 2 * (size_t)(row_base + row));
        __half* dst = sA + (size_t)row * A_STRIDE;
#pragma unroll
        for (int j = 0; j < 128; j += 2) {
            const int jj = j0 + j;
            float v0 = fmaxf(fmaf(c.x, sW1[jj + 0], fmaf(c.y, sW1[256 + jj + 0], sB1[jj + 0])), 0.f);
            float v1 = fmaxf(fmaf(c.x, sW1[jj + 1], fmaf(c.y, sW1[256 + jj + 1], sB1[jj + 1])), 0.f);
            *(__half2*)(dst + jj) = __floats2half2_rn(v0, v1);
        }
    }
    __syncthreads();

    // ldmatrix lane-address bases
    // A: lanes 0-7 rows 0..7 @k | 8-15 rows 8..15 @k | 16-23 rows 0..7 @k+8 | 24-31 rows 8..15 @k+8
    const uint32_t aA = sb + SM_A +
        (uint32_t)(((lid & 15) * A_STRIDE + ((lid & 16) ? 8 : 0)) * 2);
    // B (col-major n-major rows): lanes 0-7 n+0..7 @k | 8-15 n+0..7 @k+8 | 16-23 n+8..15 @k | 24-31 n+8..15 @k+8
    const uint32_t bB = sb + SM_B +
        (uint32_t)((nbase + (lid & 7) + ((lid & 16) ? 8 : 0)) * B_STRIDE * 2 +
                   ((lid & 8) ? 16 : 0));

    // ---- Layers 2..5 ----
#pragma unroll 1
    for (int l = 0; l < 4; l++) {
        float acc[8][4][4];
#pragma unroll
        for (int i = 0; i < 8; i++)
#pragma unroll
            for (int j = 0; j < 4; j++)
#pragma unroll
                for (int c = 0; c < 4; c++) acc[i][j][c] = 0.f;

#pragma unroll
        for (int c = 0; c < 4; c++) {
            // steady state: 3 groups may remain in flight; drain on last layer
            if (l < 3) cp_wait(3); else cp_wait(3 - c);
            __syncwarp();

#pragma unroll
            for (int ks = 0; ks < 4; ks++) {
                const int k0 = c * 64 + ks * 16;
                uint32_t b[2][4];
#pragma unroll
                for (int np = 0; np < 2; np++) {
                    const uint32_t addr = bB + (uint32_t)(np * 16 * B_STRIDE + k0) * 2;
                    LDMATRIX_X4(b[np][0], b[np][1], b[np][2], b[np][3], addr);
                }
#pragma unroll
                for (int i = 0; i < 8; i++) {
                    uint32_t a[4];
                    const uint32_t addr = aA + (uint32_t)(i * 16 * A_STRIDE + k0) * 2;
                    LDMATRIX_X4(a[0], a[1], a[2], a[3], addr);
#pragma unroll
                    for (int j = 0; j < 4; j++)
                        mma_f16(acc[i][j], a, &b[j >> 1][(j & 1) * 2]);
                }
            }

            // prefetch same chunk of next layer into the slot just consumed
            if (l < 3)
                load_wchunk(sb + SM_B, g_WtH[l + 1], nbase, c, lid);
        }

        __syncthreads();   // all warps done reading sA

        if (l < 3) {
            // epilogue: sA <- (half)relu(D + bias) for this warp's 32 cols
            const float* bias = (l == 0) ? sB2 : (l == 1) ? sB3 : sB4;
#pragma unroll
            for (int j = 0; j < 4; j++) {
                const int col = nbase + 8 * j + 2 * t;
                const float bs0 = bias[col], bs1 = bias[col + 1];
#pragma unroll
                for (int i = 0; i < 8; i++) {
                    const int row = 16 * i + g;
                    *(__half2*)(sA + (size_t)row * A_STRIDE + col) =
                        __floats2half2_rn(fmaxf(acc[i][j][0] + bs0, 0.f),
                                          fmaxf(acc[i][j][1] + bs1, 0.f));
                    *(__half2*)(sA + (size_t)(row + 8) * A_STRIDE + col) =
                        __floats2half2_rn(fmaxf(acc[i][j][2] + bs0, 0.f),
                                          fmaxf(acc[i][j][3] + bs1, 0.f));
                }
            }
            __syncthreads();
        } else {
            // ---- Layer 6: out = relu(D + b5) . W6 + b6 ----
            float r0[8], r1[8];
#pragma unroll
            for (int i = 0; i < 8; i++) { r0[i] = 0.f; r1[i] = 0.f; }
#pragma unroll
            for (int j = 0; j < 4; j++) {
                const int col = nbase + 8 * j + 2 * t;
                const float w0 = sW6[col], w1 = sW6[col + 1];
                const float s0 = sB5[col], s1 = sB5[col + 1];
#pragma unroll
                for (int i = 0; i < 8; i++) {
                    r0[i] = fmaf(fmaxf(acc[i][j][0] + s0, 0.f), w0, r0[i]);
                    r0[i] = fmaf(fmaxf(acc[i][j][1] + s1, 0.f), w1, r0[i]);
                    r1[i] = fmaf(fmaxf(acc[i][j][2] + s0, 0.f), w0, r1[i]);
                    r1[i] = fmaf(fmaxf(acc[i][j][3] + s1, 0.f), w1, r1[i]);
                }
            }
#pragma unroll
            for (int d = 1; d <= 2; d <<= 1) {
#pragma unroll
                for (int i = 0; i < 8; i++) {
                    r0[i] += __shfl_xor_sync(0xFFFFFFFFu, r0[i], d);
                    r1[i] += __shfl_xor_sync(0xFFFFFFFFu, r1[i], d);
                }
            }
            if (t == 0) {
                float* part = sPart + wid * 128;
#pragma unroll
                for (int i = 0; i < 8; i++) {
                    part[16 * i + g]     = r0[i];
                    part[16 * i + g + 8] = r1[i];
                }
            }
            __syncthreads();
            if (tid < TILE_M) {
                float s = sB6[0];
#pragma unroll
                for (int w = 0; w < 8; w++) s += sPart[w * 128 + tid];
                out[row_base + tid] = s;
            }
        }
    }
}

// ---------------------------------------------------------------------------
extern "C" void kernel_launch(void* const* d_in, const int* in_sizes, int n_in,
                              void* d_out, int out_size) {
    const float* coords = (const float*)d_in[0];
    const float* W1 = (const float*)d_in[1];
    const float* b1 = (const float*)d_in[2];
    const float* W2 = (const float*)d_in[3];
    const float* b2 = (const float*)d_in[4];
    const float* W3 = (const float*)d_in[5];
    const float* b3 = (const float*)d_in[6];
    const float* W4 = (const float*)d_in[7];
    const float* b4 = (const float*)d_in[8];
    const float* W5 = (const float*)d_in[9];
    const float* b5 = (const float*)d_in[10];
    const float* W6 = (const float*)d_in[11];
    const float* b6 = (const float*)d_in[12];
    float* out = (float*)d_out;

    const int n = in_sizes[0] / 2;  // rows

    transpose_w_kernel<<<dim3(NDIM / 32, KDIM / 32, 4), dim3(32, 8)>>>(W2, W3, W4, W5);

    cudaFuncSetAttribute(mlp_kernel, cudaFuncAttributeMaxDynamicSharedMemorySize, SMEM_TOTAL);
    mlp_kernel<<<n / TILE_M, THREADS, SMEM_TOTAL>>>(coords, W1, b1, b2, b3, b4, b5,
                                                    W6, b6, out);
}